// round 1
// baseline (speedup 1.0000x reference)
#include <cuda_runtime.h>
#include <cuda_bf16.h>
#include <math.h>

#define T 1024
#define D 768
#define H 12
#define FF 3072
#define V 8192
#define HD 64
#define NFF (H*FF)   // 36864

// ---------------- scratch (device globals; no allocation allowed) ----------
__device__ float g_xnorm[T*D];
__device__ float g_qk[T*2*D];
__device__ float g_v[H*T*HD];
__device__ float g_y[H*T*HD];
__device__ float g_x2[T*D];
__device__ float g_h[(size_t)T*NFF];      // 151 MB
__device__ float g_proj[H*T*HD];
__device__ float g_xhat[H*T*HD];
__device__ float g_recon[H*T*HD];

__constant__ float c_slopes[H] = {
    0.5f, 0.25f, 0.125f, 0.0625f, 0.03125f, 0.015625f, 0.0078125f, 0.00390625f,
    0.70710678118654752f, 0.5f, 0.35355339059327376f, 0.25f
};

__device__ __forceinline__ float gelu_exact(float x) {
    return 0.5f * x * (1.0f + erff(x * 0.70710678118654752f));
}

// ---------------- LayerNorm over 768: out = LN(a+b)*w + bb ----------------
__global__ void ln768_kernel(const float* __restrict__ a, const float* __restrict__ b,
                             const float* __restrict__ w, const float* __restrict__ bb,
                             float* __restrict__ out) {
    int t = blockIdx.x;
    int tid = threadIdx.x;                  // 256
    __shared__ float x[D];
    __shared__ float red[256];
    for (int i = tid; i < D; i += 256) x[i] = a[t*D + i] + b[t*D + i];
    __syncthreads();
    float s = 0.f;
    for (int i = tid; i < D; i += 256) s += x[i];
    red[tid] = s; __syncthreads();
    for (int st = 128; st > 0; st >>= 1) { if (tid < st) red[tid] += red[tid+st]; __syncthreads(); }
    float mu = red[0] / D;
    __syncthreads();
    float v = 0.f;
    for (int i = tid; i < D; i += 256) { float d = x[i] - mu; v += d*d; }
    red[tid] = v; __syncthreads();
    for (int st = 128; st > 0; st >>= 1) { if (tid < st) red[tid] += red[tid+st]; __syncthreads(); }
    float rs = rsqrtf(red[0]/D + 1e-5f);
    __syncthreads();
    for (int i = tid; i < D; i += 256)
        out[t*D + i] = (x[i] - mu) * rs * w[i] + bb[i];
}

// ---------------- GEMM C = A * B^T (+bias)(+act), tiled 64x64x16 ----------
// A: [M,K] row-major (lda), B: [N,K] row-major (ldb), C: [M,N] (ldc)
// batched via blockIdx.z with element strides sA,sB,sC,sBias. act: 0 none, 1 gelu
__global__ void __launch_bounds__(256) gemm_abt(
    const float* __restrict__ A, int lda, long long sA,
    const float* __restrict__ B, int ldb, long long sB,
    const float* __restrict__ bias, long long sBias,
    float* __restrict__ C, int ldc, long long sC,
    int K, int act)
{
    int z = blockIdx.z;
    A += (long long)z * sA; B += (long long)z * sB; C += (long long)z * sC;
    int bm = blockIdx.y * 64, bn = blockIdx.x * 64;
    __shared__ float As[16][64];
    __shared__ float Bs[16][64];
    int tid = threadIdx.x;
    int tx = tid & 15, ty = tid >> 4;
    float acc[4][4] = {};
    int kk = tid & 15, mrow = tid >> 4;
    for (int k0 = 0; k0 < K; k0 += 16) {
#pragma unroll
        for (int r = 0; r < 4; r++) {
            int m = mrow + 16*r;
            As[kk][m] = A[(long long)(bm + m)*lda + k0 + kk];
            Bs[kk][m] = B[(long long)(bn + m)*ldb + k0 + kk];
        }
        __syncthreads();
#pragma unroll
        for (int k = 0; k < 16; k++) {
            float a0 = As[k][ty*4+0], a1 = As[k][ty*4+1], a2 = As[k][ty*4+2], a3 = As[k][ty*4+3];
            float b0 = Bs[k][tx*4+0], b1 = Bs[k][tx*4+1], b2 = Bs[k][tx*4+2], b3 = Bs[k][tx*4+3];
            acc[0][0] += a0*b0; acc[0][1] += a0*b1; acc[0][2] += a0*b2; acc[0][3] += a0*b3;
            acc[1][0] += a1*b0; acc[1][1] += a1*b1; acc[1][2] += a1*b2; acc[1][3] += a1*b3;
            acc[2][0] += a2*b0; acc[2][1] += a2*b1; acc[2][2] += a2*b2; acc[2][3] += a2*b3;
            acc[3][0] += a3*b0; acc[3][1] += a3*b1; acc[3][2] += a3*b2; acc[3][3] += a3*b3;
        }
        __syncthreads();
    }
#pragma unroll
    for (int i = 0; i < 4; i++) {
        int m = bm + ty*4 + i;
#pragma unroll
        for (int j = 0; j < 4; j++) {
            int n = bn + tx*4 + j;
            float vv = acc[i][j];
            if (bias) vv += bias[(long long)z*sBias + n];
            if (act == 1) vv = gelu_exact(vv);
            C[(long long)m*ldc + n] = vv;
        }
    }
}

// ---------------- GEMM C = A * B, tiled 64x64x16 --------------------------
// A: [M,K] row-major (lda), B: [K,N] row-major (ldb)
__global__ void __launch_bounds__(256) gemm_ab(
    const float* __restrict__ A, int lda, long long sA,
    const float* __restrict__ B, int ldb, long long sB,
    float* __restrict__ C, int ldc, long long sC,
    int K)
{
    int z = blockIdx.z;
    A += (long long)z * sA; B += (long long)z * sB; C += (long long)z * sC;
    int bm = blockIdx.y * 64, bn = blockIdx.x * 64;
    __shared__ float As[16][64];
    __shared__ float Bs[16][64];
    int tid = threadIdx.x;
    int tx = tid & 15, ty = tid >> 4;
    float acc[4][4] = {};
    int kk = tid & 15, mrow = tid >> 4;
    int bn_col = tid & 63, bk_row = tid >> 6;
    for (int k0 = 0; k0 < K; k0 += 16) {
#pragma unroll
        for (int r = 0; r < 4; r++) {
            int m = mrow + 16*r;
            As[kk][m] = A[(long long)(bm + m)*lda + k0 + kk];
            int kb = bk_row + 4*r;
            Bs[kb][bn_col] = B[(long long)(k0 + kb)*ldb + bn + bn_col];
        }
        __syncthreads();
#pragma unroll
        for (int k = 0; k < 16; k++) {
            float a0 = As[k][ty*4+0], a1 = As[k][ty*4+1], a2 = As[k][ty*4+2], a3 = As[k][ty*4+3];
            float b0 = Bs[k][tx*4+0], b1 = Bs[k][tx*4+1], b2 = Bs[k][tx*4+2], b3 = Bs[k][tx*4+3];
            acc[0][0] += a0*b0; acc[0][1] += a0*b1; acc[0][2] += a0*b2; acc[0][3] += a0*b3;
            acc[1][0] += a1*b0; acc[1][1] += a1*b1; acc[1][2] += a1*b2; acc[1][3] += a1*b3;
            acc[2][0] += a2*b0; acc[2][1] += a2*b1; acc[2][2] += a2*b2; acc[2][3] += a2*b3;
            acc[3][0] += a3*b0; acc[3][1] += a3*b1; acc[3][2] += a3*b2; acc[3][3] += a3*b3;
        }
        __syncthreads();
    }
#pragma unroll
    for (int i = 0; i < 4; i++) {
        int m = bm + ty*4 + i;
#pragma unroll
        for (int j = 0; j < 4; j++)
            C[(long long)m*ldc + bn + tx*4 + j] = acc[i][j];
    }
}

// ---------------- v = einsum('ij,tjd->itd', v_fact, xt_heads) -------------
__global__ void vproj_kernel(const float* __restrict__ xt, const float* __restrict__ vf,
                             float* __restrict__ v) {
    int t = blockIdx.x, h = blockIdx.y, d = threadIdx.x;   // 64 threads
    float acc = 0.f;
#pragma unroll
    for (int j = 0; j < H; j++) acc += vf[h*H + j] * xt[t*D + j*HD + d];
    v[(h*T + t)*HD + d] = acc;
}

// ---------------- causal attention with ALiBi, one block per (qi, h) ------
__global__ void attn_kernel(const float* __restrict__ qk, const float* __restrict__ v,
                            float* __restrict__ y) {
    int qi = blockIdx.x, h = blockIdx.y;
    int tid = threadIdx.x;                 // 128
    __shared__ float qrow[HD];
    __shared__ float sc[T];
    __shared__ float red[128];
    if (tid < HD) qrow[tid] = qk[(long long)qi*(2*D) + h*HD + tid];
    __syncthreads();
    float slope = c_slopes[h];
    float m = -INFINITY;
    for (int j = tid; j <= qi; j += 128) {
        const float* krow = qk + (long long)j*(2*D) + D + h*HD;
        float dot = 0.f;
#pragma unroll
        for (int e = 0; e < HD; e++) dot += qrow[e] * krow[e];
        float s = dot * 0.125f + slope * (float)(j - qi);
        sc[j] = s;
        m = fmaxf(m, s);
    }
    red[tid] = m; __syncthreads();
    for (int st = 64; st > 0; st >>= 1) { if (tid < st) red[tid] = fmaxf(red[tid], red[tid+st]); __syncthreads(); }
    m = red[0];
    __syncthreads();
    float lsum = 0.f;
    for (int j = tid; j <= qi; j += 128) { float p = expf(sc[j] - m); sc[j] = p; lsum += p; }
    red[tid] = lsum; __syncthreads();
    for (int st = 64; st > 0; st >>= 1) { if (tid < st) red[tid] += red[tid+st]; __syncthreads(); }
    float inv = 1.0f / red[0];
    __syncthreads();
    if (tid < HD) {
        const float* vh = v + (long long)h*T*HD;
        float acc = 0.f;
        for (int j = 0; j <= qi; j++) acc += sc[j] * vh[j*HD + tid];
        y[((long long)h*T + qi)*HD + tid] = acc * inv;
    }
}

// ---------------- xt_new = xt + out_fact-lift(y) --------------------------
__global__ void mixout_kernel(const float* __restrict__ xt, const float* __restrict__ of,
                              const float* __restrict__ y, float* __restrict__ xt_new) {
    int t = blockIdx.x, c = threadIdx.x;   // 768 threads
    int i = c >> 6, d = c & 63;
    float acc = xt[t*D + c];
#pragma unroll
    for (int j = 0; j < H; j++) acc += of[i*H + j] * y[((long long)j*T + t)*HD + d];
    xt_new[t*D + c] = acc;
}

// ---------------- per-head LN over 64 -------------------------------------
__global__ void dln_kernel(const float* __restrict__ p, const float* __restrict__ w,
                           const float* __restrict__ b, float* __restrict__ xhat) {
    int row = blockIdx.x;                  // h*T + t
    int h = row >> 10;
    int tid = threadIdx.x;                 // 64
    __shared__ float r[64];
    float x = p[(long long)row*HD + tid];
    r[tid] = x; __syncthreads();
    for (int st = 32; st > 0; st >>= 1) { if (tid < st) r[tid] += r[tid+st]; __syncthreads(); }
    float mu = r[0] / HD;
    __syncthreads();
    float d = x - mu;
    r[tid] = d*d; __syncthreads();
    for (int st = 32; st > 0; st >>= 1) { if (tid < st) r[tid] += r[tid+st]; __syncthreads(); }
    float rs = rsqrtf(r[0]/HD + 1e-5f);
    xhat[(long long)row*HD + tid] = d * rs * w[h*HD + tid] + b[h*HD + tid];
}

// ---------------- in-place softmax over V=8192 ----------------------------
__global__ void dsoftmax_kernel(float* __restrict__ dw) {
    long long row = blockIdx.x;            // 12288 rows
    float* p = dw + row * V;
    int tid = threadIdx.x;                 // 256
    __shared__ float sh[V];
    __shared__ float red[256];
    float m = -INFINITY;
    for (int i = tid; i < V; i += 256) { float x = p[i]; sh[i] = x; m = fmaxf(m, x); }
    red[tid] = m; __syncthreads();
    for (int st = 128; st > 0; st >>= 1) { if (tid < st) red[tid] = fmaxf(red[tid], red[tid+st]); __syncthreads(); }
    m = red[0];
    __syncthreads();
    float s = 0.f;
    for (int i = tid; i < V; i += 256) { float e = expf(sh[i] - m); sh[i] = e; s += e; }
    red[tid] = s; __syncthreads();
    for (int st = 128; st > 0; st >>= 1) { if (tid < st) red[tid] += red[tid+st]; __syncthreads(); }
    float inv = 1.0f / red[0];
    __syncthreads();
    for (int i = tid; i < V; i += 256) p[i] = sh[i] * inv;
}

// ---------------- loss + xe_new -------------------------------------------
__global__ void zero_loss_kernel(float* loss) { *loss = 0.f; }

__global__ void loss_kernel(const float* __restrict__ xhat, const float* __restrict__ recon,
                            float* __restrict__ loss) {
    int row = blockIdx.x;                  // 12288
    int tid = threadIdx.x;                 // 64
    __shared__ float r[64];
    float d = xhat[(long long)row*HD + tid] - recon[(long long)row*HD + tid];
    r[tid] = d*d; __syncthreads();
    for (int st = 32; st > 0; st >>= 1) { if (tid < st) r[tid] += r[tid+st]; __syncthreads(); }
    if (tid == 0) atomicAdd(loss, r[0] * (1.0f / (float)(H*T*HD)));
}

__global__ void xenew_kernel(const float* __restrict__ xe, const float* __restrict__ recon,
                             float* __restrict__ out_xe) {
    int t = blockIdx.x, c = threadIdx.x;   // 768
    int h = c >> 6, e = c & 63;
    out_xe[t*D + c] = xe[t*D + c] + recon[((long long)h*T + t)*HD + e];
}

// ---------------- launch ---------------------------------------------------
extern "C" void kernel_launch(void* const* d_in, const int* in_sizes, int n_in,
                              void* d_out, int out_size) {
    const float* xt      = (const float*)d_in[0];
    const float* xe      = (const float*)d_in[1];
    const float* ln1_w   = (const float*)d_in[2];
    const float* ln1_b   = (const float*)d_in[3];
    const float* qk_w    = (const float*)d_in[4];
    const float* qk_b    = (const float*)d_in[5];
    const float* v_fact  = (const float*)d_in[6];
    const float* out_fact= (const float*)d_in[7];
    const float* ln2_w   = (const float*)d_in[8];
    const float* ln2_b   = (const float*)d_in[9];
    const float* fc_w    = (const float*)d_in[10];
    const float* fc_b    = (const float*)d_in[11];
    const float* proj_w  = (const float*)d_in[12];
    const float* proj_b  = (const float*)d_in[13];
    const float* dln_w   = (const float*)d_in[14];
    const float* dln_b   = (const float*)d_in[15];
    const float* dict_emb= (const float*)d_in[16];

    float* out = (float*)d_out;
    float* out_xt = out;                       // [T,D]
    float* out_xe = out + (size_t)T*D;         // [T,D]
    float* out_dw = out + (size_t)2*T*D;       // [H,T,V]
    float* out_loss = out + (size_t)2*T*D + (size_t)H*T*V; // scalar

    float *xnorm, *qkbuf, *vbuf, *ybuf, *x2, *hbuf, *pbuf, *xhat, *recon;
    cudaGetSymbolAddress((void**)&xnorm, g_xnorm);
    cudaGetSymbolAddress((void**)&qkbuf, g_qk);
    cudaGetSymbolAddress((void**)&vbuf,  g_v);
    cudaGetSymbolAddress((void**)&ybuf,  g_y);
    cudaGetSymbolAddress((void**)&x2,    g_x2);
    cudaGetSymbolAddress((void**)&hbuf,  g_h);
    cudaGetSymbolAddress((void**)&pbuf,  g_proj);
    cudaGetSymbolAddress((void**)&xhat,  g_xhat);
    cudaGetSymbolAddress((void**)&recon, g_recon);

    // 1. x_norm = LN1(xt + xe)
    ln768_kernel<<<T, 256>>>(xt, xe, ln1_w, ln1_b, xnorm);
    // 2. qk = x_norm @ qk_w^T + qk_b   [1024, 1536]
    gemm_abt<<<dim3(2*D/64, T/64, 1), 256>>>(xnorm, D, 0, qk_w, D, 0, qk_b, 0,
                                             qkbuf, 2*D, 0, D, 0);
    // 3. v lift
    vproj_kernel<<<dim3(T, H), HD>>>(xt, v_fact, vbuf);
    // 4. attention
    attn_kernel<<<dim3(T, H), 128>>>(qkbuf, vbuf, ybuf);
    // 5. xt_new = xt + out_fact-lift(y)   -> d_out
    mixout_kernel<<<T, D>>>(xt, out_fact, ybuf, out_xt);
    // 6. x2 = LN2(xt_new + xe)
    ln768_kernel<<<T, 256>>>(out_xt, xe, ln2_w, ln2_b, x2);
    // 7. h = gelu(x2 @ fc_w_flat^T + fc_b)   [1024, 36864]
    gemm_abt<<<dim3(NFF/64, T/64, 1), 256>>>(x2, D, 0, fc_w, D, 0, fc_b, 0,
                                             hbuf, NFF, 0, D, 1);
    // 8. proj (batched over heads): [1024,64] per head
    gemm_abt<<<dim3(1, T/64, H), 256>>>(hbuf, NFF, FF, proj_w, FF, (long long)HD*FF,
                                        proj_b, HD, pbuf, HD, (long long)T*HD, FF, 0);
    // 9. per-head LN
    dln_kernel<<<H*T, HD>>>(pbuf, dln_w, dln_b, xhat);
    // 10. dict logits -> out_dw  (batched)
    gemm_abt<<<dim3(V/64, T/64, H), 256>>>(xhat, HD, (long long)T*HD,
                                           dict_emb, HD, (long long)V*HD,
                                           nullptr, 0,
                                           out_dw, V, (long long)T*V, HD, 0);
    // 11. softmax in place
    dsoftmax_kernel<<<H*T, 256>>>(out_dw);
    // 12. recon = weights @ dict_emb  (batched, C = A*B)
    gemm_ab<<<dim3(1, T/64, H), 256>>>(out_dw, V, (long long)T*V,
                                       dict_emb, HD, (long long)V*HD,
                                       recon, HD, (long long)T*HD, V);
    // 13/14. loss
    zero_loss_kernel<<<1, 1>>>(out_loss);
    loss_kernel<<<H*T, HD>>>(xhat, recon, out_loss);
    // 15. xe_new
    xenew_kernel<<<T, D>>>(xe, recon, out_xe);
}

// round 2
// speedup vs baseline: 2.1285x; 2.1285x over previous
#include <cuda_runtime.h>
#include <cuda_bf16.h>
#include <mma.h>
#include <math.h>

using namespace nvcuda;

#define T 1024
#define D 768
#define H 12
#define FF 3072
#define V 8192
#define HD 64
#define NFF (H*FF)   // 36864

// ---------------- scratch (device globals; no allocation allowed) ----------
__device__ float g_xnorm[T*D];
__device__ float g_qk[T*2*D];
__device__ float g_v[H*T*HD];
__device__ float g_y[H*T*HD];
__device__ float g_x2[T*D];
__device__ float g_h[(size_t)T*NFF];      // 151 MB fp32
__device__ float g_proj[H*T*HD];
__device__ float g_xhat[H*T*HD];
__device__ float g_recon[H*T*HD];

__constant__ float c_slopes[H] = {
    0.5f, 0.25f, 0.125f, 0.0625f, 0.03125f, 0.015625f, 0.0078125f, 0.00390625f,
    0.70710678118654752f, 0.5f, 0.35355339059327376f, 0.25f
};

__device__ __forceinline__ float gelu_exact(float x) {
    return 0.5f * x * (1.0f + erff(x * 0.70710678118654752f));
}

// ---------------- LayerNorm over 768: out = LN(a+b)*w + bb ----------------
__global__ void ln768_kernel(const float* __restrict__ a, const float* __restrict__ b,
                             const float* __restrict__ w, const float* __restrict__ bb,
                             float* __restrict__ out) {
    int t = blockIdx.x;
    int tid = threadIdx.x;                  // 256
    __shared__ float x[D];
    __shared__ float red[256];
    for (int i = tid; i < D; i += 256) x[i] = a[t*D + i] + b[t*D + i];
    __syncthreads();
    float s = 0.f;
    for (int i = tid; i < D; i += 256) s += x[i];
    red[tid] = s; __syncthreads();
    for (int st = 128; st > 0; st >>= 1) { if (tid < st) red[tid] += red[tid+st]; __syncthreads(); }
    float mu = red[0] / D;
    __syncthreads();
    float v = 0.f;
    for (int i = tid; i < D; i += 256) { float d = x[i] - mu; v += d*d; }
    red[tid] = v; __syncthreads();
    for (int st = 128; st > 0; st >>= 1) { if (tid < st) red[tid] += red[tid+st]; __syncthreads(); }
    float rs = rsqrtf(red[0]/D + 1e-5f);
    __syncthreads();
    for (int i = tid; i < D; i += 256)
        out[t*D + i] = (x[i] - mu) * rs * w[i] + bb[i];
}

// ============================================================================
// WMMA bf16 GEMM, fp32 in/out (convert on smem load), fp32 accumulate.
//   BTRANS=0: C = A[M,K] * B[N,K]^T      (both k-major)
//   BTRANS=1: C = A[M,K] * B[K,N]        (B row-major [K,N], needs BN==64)
//   ACT=1: exact GELU on output. bias optional (per-n, batched stride sBias).
// Tiles: BM x BN x 32, 8 warps (256 threads), warp tile WM x WN.
// ============================================================================
template<int BM, int BN, int WM, int WN, int BTRANS, int ACT>
__global__ void __launch_bounds__(256) wgemm(
    const float* __restrict__ A, int lda, long long sA,
    const float* __restrict__ B, int ldb, long long sB,
    const float* __restrict__ bias, long long sBias,
    float* __restrict__ C, int ldc, long long sC, int K)
{
    constexpr int BK = 32;
    constexpr int BKP = 48;    // padded stride (96 B: 32B-aligned rows, conflict-free-ish)
    __shared__ __nv_bfloat16 As[BM * BKP];
    __shared__ __nv_bfloat16 Bs[BN * BKP];
    __shared__ float stage[8][16*16];

    int z = blockIdx.z;
    A += (long long)z * sA; B += (long long)z * sB; C += (long long)z * sC;
    int bm = blockIdx.y * BM, bn = blockIdx.x * BN;
    int tid = threadIdx.x, wid = tid >> 5, lane = tid & 31;
    constexpr int WCOLS = BN / WN;
    int wm0 = (wid / WCOLS) * WM;
    int wn0 = (wid % WCOLS) * WN;
    constexpr int MF = WM/16, NF = WN/16;

    wmma::fragment<wmma::accumulator,16,16,16,float> fc[MF][NF];
#pragma unroll
    for (int i = 0; i < MF; i++)
#pragma unroll
        for (int j = 0; j < NF; j++) wmma::fill_fragment(fc[i][j], 0.0f);

    for (int k0 = 0; k0 < K; k0 += BK) {
        // --- A tile: [BM x 32] fp32 -> bf16, float4 loads (k-major) ---
        {
            int r = tid >> 3, kq = tid & 7;
#pragma unroll
            for (int it = 0; it < BM/32; it++) {
                int m = r + it*32;
                float4 vv = *(const float4*)(A + (long long)(bm + m)*lda + k0 + kq*4);
                __nv_bfloat16* p = &As[m*BKP + kq*4];
                p[0] = __float2bfloat16(vv.x); p[1] = __float2bfloat16(vv.y);
                p[2] = __float2bfloat16(vv.z); p[3] = __float2bfloat16(vv.w);
            }
        }
        // --- B tile ---
        if (BTRANS == 0) {
            int r = tid >> 3, kq = tid & 7;
#pragma unroll
            for (int it = 0; it < BN/32; it++) {
                int n = r + it*32;
                float4 vv = *(const float4*)(B + (long long)(bn + n)*ldb + k0 + kq*4);
                __nv_bfloat16* p = &Bs[n*BKP + kq*4];
                p[0] = __float2bfloat16(vv.x); p[1] = __float2bfloat16(vv.y);
                p[2] = __float2bfloat16(vv.z); p[3] = __float2bfloat16(vv.w);
            }
        } else {
            // B is [K,N], BN==64: coalesced over n, transpose into Bs[n][k]
            int n = tid & (BN - 1);
            int kb = (tid / BN) * (BK*BN/256);
#pragma unroll
            for (int i = 0; i < BK*BN/256; i++) {
                int k = kb + i;
                Bs[n*BKP + k] = __float2bfloat16(B[(long long)(k0 + k)*ldb + bn + n]);
            }
        }
        __syncthreads();

#pragma unroll
        for (int kk = 0; kk < BK; kk += 16) {
            wmma::fragment<wmma::matrix_a,16,16,16,__nv_bfloat16,wmma::row_major> fa[MF];
            wmma::fragment<wmma::matrix_b,16,16,16,__nv_bfloat16,wmma::col_major> fb[NF];
#pragma unroll
            for (int i = 0; i < MF; i++)
                wmma::load_matrix_sync(fa[i], &As[(wm0 + i*16)*BKP + kk], BKP);
#pragma unroll
            for (int j = 0; j < NF; j++)
                wmma::load_matrix_sync(fb[j], &Bs[(wn0 + j*16)*BKP + kk], BKP);
#pragma unroll
            for (int i = 0; i < MF; i++)
#pragma unroll
                for (int j = 0; j < NF; j++)
                    wmma::mma_sync(fc[i][j], fa[i], fb[j], fc[i][j]);
        }
        __syncthreads();
    }

    // --- epilogue: stage each 16x16 frag in smem, apply bias/act, write ---
    float* st = stage[wid];
#pragma unroll
    for (int i = 0; i < MF; i++) {
#pragma unroll
        for (int j = 0; j < NF; j++) {
            wmma::store_matrix_sync(st, fc[i][j], 16, wmma::mem_row_major);
            __syncwarp();
            int m0 = bm + wm0 + i*16, n0 = bn + wn0 + j*16;
#pragma unroll
            for (int e = 0; e < 8; e++) {
                int idx = e*32 + lane;
                int r = idx >> 4, c = idx & 15;
                float val = st[idx];
                int n = n0 + c;
                if (bias) val += bias[(long long)z*sBias + n];
                if (ACT == 1) val = gelu_exact(val);
                C[(long long)(m0 + r)*ldc + n] = val;
            }
            __syncwarp();
        }
    }
}

// ---------------- v = einsum('ij,tjd->itd', v_fact, xt_heads) -------------
__global__ void vproj_kernel(const float* __restrict__ xt, const float* __restrict__ vf,
                             float* __restrict__ v) {
    int t = blockIdx.x, h = blockIdx.y, d = threadIdx.x;   // 64 threads
    float acc = 0.f;
#pragma unroll
    for (int j = 0; j < H; j++) acc += vf[h*H + j] * xt[t*D + j*HD + d];
    v[(h*T + t)*HD + d] = acc;
}

// ---------------- causal attention with ALiBi, one block per (qi, h) ------
__global__ void attn_kernel(const float* __restrict__ qk, const float* __restrict__ v,
                            float* __restrict__ y) {
    int qi = blockIdx.x, h = blockIdx.y;
    int tid = threadIdx.x;                 // 128
    __shared__ float qrow[HD];
    __shared__ float sc[T];
    __shared__ float red[128];
    if (tid < HD) qrow[tid] = qk[(long long)qi*(2*D) + h*HD + tid];
    __syncthreads();
    float slope = c_slopes[h];
    float m = -INFINITY;
    for (int j = tid; j <= qi; j += 128) {
        const float* krow = qk + (long long)j*(2*D) + D + h*HD;
        float dot = 0.f;
#pragma unroll
        for (int e = 0; e < HD; e++) dot += qrow[e] * krow[e];
        float s = dot * 0.125f + slope * (float)(j - qi);
        sc[j] = s;
        m = fmaxf(m, s);
    }
    red[tid] = m; __syncthreads();
    for (int st = 64; st > 0; st >>= 1) { if (tid < st) red[tid] = fmaxf(red[tid], red[tid+st]); __syncthreads(); }
    m = red[0];
    __syncthreads();
    float lsum = 0.f;
    for (int j = tid; j <= qi; j += 128) { float p = expf(sc[j] - m); sc[j] = p; lsum += p; }
    red[tid] = lsum; __syncthreads();
    for (int st = 64; st > 0; st >>= 1) { if (tid < st) red[tid] += red[tid+st]; __syncthreads(); }
    float inv = 1.0f / red[0];
    __syncthreads();
    if (tid < HD) {
        const float* vh = v + (long long)h*T*HD;
        float acc = 0.f;
        for (int j = 0; j <= qi; j++) acc += sc[j] * vh[j*HD + tid];
        y[((long long)h*T + qi)*HD + tid] = acc * inv;
    }
}

// ---------------- xt_new = xt + out_fact-lift(y) --------------------------
__global__ void mixout_kernel(const float* __restrict__ xt, const float* __restrict__ of,
                              const float* __restrict__ y, float* __restrict__ xt_new) {
    int t = blockIdx.x, c = threadIdx.x;   // 768 threads
    int i = c >> 6, d = c & 63;
    float acc = xt[t*D + c];
#pragma unroll
    for (int j = 0; j < H; j++) acc += of[i*H + j] * y[((long long)j*T + t)*HD + d];
    xt_new[t*D + c] = acc;
}

// ---------------- per-head LN over 64 -------------------------------------
__global__ void dln_kernel(const float* __restrict__ p, const float* __restrict__ w,
                           const float* __restrict__ b, float* __restrict__ xhat) {
    int row = blockIdx.x;                  // h*T + t
    int h = row >> 10;
    int tid = threadIdx.x;                 // 64
    __shared__ float r[64];
    float x = p[(long long)row*HD + tid];
    r[tid] = x; __syncthreads();
    for (int st = 32; st > 0; st >>= 1) { if (tid < st) r[tid] += r[tid+st]; __syncthreads(); }
    float mu = r[0] / HD;
    __syncthreads();
    float d = x - mu;
    r[tid] = d*d; __syncthreads();
    for (int st = 32; st > 0; st >>= 1) { if (tid < st) r[tid] += r[tid+st]; __syncthreads(); }
    float rs = rsqrtf(r[0]/HD + 1e-5f);
    xhat[(long long)row*HD + tid] = d * rs * w[h*HD + tid] + b[h*HD + tid];
}

// ---------------- in-place softmax over V=8192 ----------------------------
__global__ void dsoftmax_kernel(float* __restrict__ dw) {
    long long row = blockIdx.x;            // 12288 rows
    float* p = dw + row * V;
    int tid = threadIdx.x;                 // 256
    __shared__ float sh[V];
    __shared__ float red[256];
    float m = -INFINITY;
    for (int i = tid; i < V; i += 256) { float x = p[i]; sh[i] = x; m = fmaxf(m, x); }
    red[tid] = m; __syncthreads();
    for (int st = 128; st > 0; st >>= 1) { if (tid < st) red[tid] = fmaxf(red[tid], red[tid+st]); __syncthreads(); }
    m = red[0];
    __syncthreads();
    float s = 0.f;
    for (int i = tid; i < V; i += 256) { float e = expf(sh[i] - m); sh[i] = e; s += e; }
    red[tid] = s; __syncthreads();
    for (int st = 128; st > 0; st >>= 1) { if (tid < st) red[tid] += red[tid+st]; __syncthreads(); }
    float inv = 1.0f / red[0];
    __syncthreads();
    for (int i = tid; i < V; i += 256) p[i] = sh[i] * inv;
}

// ---------------- loss + xe_new -------------------------------------------
__global__ void zero_loss_kernel(float* loss) { *loss = 0.f; }

__global__ void loss_kernel(const float* __restrict__ xhat, const float* __restrict__ recon,
                            float* __restrict__ loss) {
    int row = blockIdx.x;                  // 12288
    int tid = threadIdx.x;                 // 64
    __shared__ float r[64];
    float d = xhat[(long long)row*HD + tid] - recon[(long long)row*HD + tid];
    r[tid] = d*d; __syncthreads();
    for (int st = 32; st > 0; st >>= 1) { if (tid < st) r[tid] += r[tid+st]; __syncthreads(); }
    if (tid == 0) atomicAdd(loss, r[0] * (1.0f / (float)(H*T*HD)));
}

__global__ void xenew_kernel(const float* __restrict__ xe, const float* __restrict__ recon,
                             float* __restrict__ out_xe) {
    int t = blockIdx.x, c = threadIdx.x;   // 768
    int h = c >> 6, e = c & 63;
    out_xe[t*D + c] = xe[t*D + c] + recon[((long long)h*T + t)*HD + e];
}

// ---------------- launch ---------------------------------------------------
extern "C" void kernel_launch(void* const* d_in, const int* in_sizes, int n_in,
                              void* d_out, int out_size) {
    const float* xt      = (const float*)d_in[0];
    const float* xe      = (const float*)d_in[1];
    const float* ln1_w   = (const float*)d_in[2];
    const float* ln1_b   = (const float*)d_in[3];
    const float* qk_w    = (const float*)d_in[4];
    const float* qk_b    = (const float*)d_in[5];
    const float* v_fact  = (const float*)d_in[6];
    const float* out_fact= (const float*)d_in[7];
    const float* ln2_w   = (const float*)d_in[8];
    const float* ln2_b   = (const float*)d_in[9];
    const float* fc_w    = (const float*)d_in[10];
    const float* fc_b    = (const float*)d_in[11];
    const float* proj_w  = (const float*)d_in[12];
    const float* proj_b  = (const float*)d_in[13];
    const float* dln_w   = (const float*)d_in[14];
    const float* dln_b   = (const float*)d_in[15];
    const float* dict_emb= (const float*)d_in[16];

    float* out = (float*)d_out;
    float* out_xt = out;                       // [T,D]
    float* out_xe = out + (size_t)T*D;         // [T,D]
    float* out_dw = out + (size_t)2*T*D;       // [H,T,V]
    float* out_loss = out + (size_t)2*T*D + (size_t)H*T*V; // scalar

    float *xnorm, *qkbuf, *vbuf, *ybuf, *x2, *hbuf, *pbuf, *xhat, *recon;
    cudaGetSymbolAddress((void**)&xnorm, g_xnorm);
    cudaGetSymbolAddress((void**)&qkbuf, g_qk);
    cudaGetSymbolAddress((void**)&vbuf,  g_v);
    cudaGetSymbolAddress((void**)&ybuf,  g_y);
    cudaGetSymbolAddress((void**)&x2,    g_x2);
    cudaGetSymbolAddress((void**)&hbuf,  g_h);
    cudaGetSymbolAddress((void**)&pbuf,  g_proj);
    cudaGetSymbolAddress((void**)&xhat,  g_xhat);
    cudaGetSymbolAddress((void**)&recon, g_recon);

    // 1. x_norm = LN1(xt + xe)
    ln768_kernel<<<T, 256>>>(xt, xe, ln1_w, ln1_b, xnorm);
    // 2. qk = x_norm @ qk_w^T + qk_b   [1024, 1536]
    wgemm<128,128,64,32,0,0><<<dim3(2*D/128, T/128, 1), 256>>>(
        xnorm, D, 0, qk_w, D, 0, qk_b, 0, qkbuf, 2*D, 0, D);
    // 3. v lift
    vproj_kernel<<<dim3(T, H), HD>>>(xt, v_fact, vbuf);
    // 4. attention
    attn_kernel<<<dim3(T, H), 128>>>(qkbuf, vbuf, ybuf);
    // 5. xt_new = xt + out_fact-lift(y)   -> d_out
    mixout_kernel<<<T, D>>>(xt, out_fact, ybuf, out_xt);
    // 6. x2 = LN2(xt_new + xe)
    ln768_kernel<<<T, 256>>>(out_xt, xe, ln2_w, ln2_b, x2);
    // 7. h = gelu(x2 @ fc_w_flat^T + fc_b)   [1024, 36864]
    wgemm<128,128,64,32,0,1><<<dim3(NFF/128, T/128, 1), 256>>>(
        x2, D, 0, fc_w, D, 0, fc_b, 0, hbuf, NFF, 0, D);
    // 8. proj (batched over heads): [1024,64] per head, K=3072
    wgemm<128,64,32,32,0,0><<<dim3(1, T/128, H), 256>>>(
        hbuf, NFF, FF, proj_w, FF, (long long)HD*FF,
        proj_b, HD, pbuf, HD, (long long)T*HD, FF);
    // 9. per-head LN
    dln_kernel<<<H*T, HD>>>(pbuf, dln_w, dln_b, xhat);
    // 10. dict logits -> out_dw  (batched, K=64)
    wgemm<128,128,64,32,0,0><<<dim3(V/128, T/128, H), 256>>>(
        xhat, HD, (long long)T*HD, dict_emb, HD, (long long)V*HD,
        nullptr, 0, out_dw, V, (long long)T*V, HD);
    // 11. softmax in place
    dsoftmax_kernel<<<H*T, 256>>>(out_dw);
    // 12. recon = weights @ dict_emb  (batched, C = A*B, B is [K=V, N=HD])
    wgemm<128,64,32,32,1,0><<<dim3(1, T/128, H), 256>>>(
        out_dw, V, (long long)T*V, dict_emb, HD, (long long)V*HD,
        nullptr, 0, recon, HD, (long long)T*HD, V);
    // 13/14. loss
    zero_loss_kernel<<<1, 1>>>(out_loss);
    loss_kernel<<<H*T, HD>>>(xhat, recon, out_loss);
    // 15. xe_new
    xenew_kernel<<<T, D>>>(xe, recon, out_xe);
}

// round 3
// speedup vs baseline: 4.8913x; 2.2980x over previous
#include <cuda_runtime.h>
#include <cuda_bf16.h>
#include <mma.h>
#include <math.h>
#include <stdint.h>

using namespace nvcuda;

#define T 1024
#define D 768
#define H 12
#define FF 3072
#define V 8192
#define HD 64
#define NFF (H*FF)   // 36864

typedef __nv_bfloat16 bf16;

// ---------------- scratch (device globals; no allocation allowed) ----------
__device__ bf16  g_xnorm_bf[T*D];
__device__ float g_qk[T*2*D];
__device__ bf16  g_qkw_bf[2*D*D];
__device__ bf16  g_fcw_bf[(size_t)NFF*D];       // 56.6 MB (L2-resident)
__device__ bf16  g_projw_bf[H*HD*FF];
__device__ bf16  g_dict_bf[H*V*HD];
__device__ bf16  g_x2_bf[T*D];
__device__ bf16  g_h_bf[(size_t)T*NFF];         // 75.5 MB
__device__ float g_v[H*T*HD];
__device__ float g_y[H*T*HD];
__device__ float g_proj[H*T*HD];
__device__ float g_xhat[H*T*HD];
__device__ bf16  g_xhat_bf[H*T*HD];
__device__ bf16  g_probs_bf[(size_t)H*T*V];     // 201 MB
__device__ float g_recon[H*T*HD];

__constant__ float c_slopes[H] = {
    0.5f, 0.25f, 0.125f, 0.0625f, 0.03125f, 0.015625f, 0.0078125f, 0.00390625f,
    0.70710678118654752f, 0.5f, 0.35355339059327376f, 0.25f
};

__device__ __forceinline__ float gelu_exact(float x) {
    return 0.5f * x * (1.0f + erff(x * 0.70710678118654752f));
}

__device__ __forceinline__ uint32_t smem_u32(const void* p) {
    return (uint32_t)__cvta_generic_to_shared(p);
}
#define CP_ASYNC16(dst_u32, src) \
    asm volatile("cp.async.cg.shared.global [%0], [%1], 16;\n" :: "r"(dst_u32), "l"(src))
#define CP_COMMIT() asm volatile("cp.async.commit_group;\n")
#define CP_WAIT1()  asm volatile("cp.async.wait_group 1;\n")

template<typename OutT> __device__ __forceinline__ OutT to_out(float v);
template<> __device__ __forceinline__ float to_out<float>(float v) { return v; }
template<> __device__ __forceinline__ bf16  to_out<bf16>(float v)  { return __float2bfloat16(v); }

// ---------------- fp32 -> bf16 bulk convert (8 elems / thread) ------------
__global__ void f2bf_kernel(const float4* __restrict__ in, uint4* __restrict__ out, int n8) {
    int i = blockIdx.x * 256 + threadIdx.x;
    if (i < n8) {
        float4 a = in[2*i], b = in[2*i+1];
        __nv_bfloat162 p0 = __float22bfloat162_rn(make_float2(a.x, a.y));
        __nv_bfloat162 p1 = __float22bfloat162_rn(make_float2(a.z, a.w));
        __nv_bfloat162 p2 = __float22bfloat162_rn(make_float2(b.x, b.y));
        __nv_bfloat162 p3 = __float22bfloat162_rn(make_float2(b.z, b.w));
        uint4 o;
        o.x = *(uint32_t*)&p0; o.y = *(uint32_t*)&p1;
        o.z = *(uint32_t*)&p2; o.w = *(uint32_t*)&p3;
        out[i] = o;
    }
}

// ---------------- LayerNorm over 768: out_bf = LN(a+b)*w + bb -------------
__global__ void ln768_kernel(const float* __restrict__ a, const float* __restrict__ b,
                             const float* __restrict__ w, const float* __restrict__ bb,
                             bf16* __restrict__ out) {
    int t = blockIdx.x;
    int tid = threadIdx.x;                  // 256
    __shared__ float x[D];
    __shared__ float red[256];
    for (int i = tid; i < D; i += 256) x[i] = a[t*D + i] + b[t*D + i];
    __syncthreads();
    float s = 0.f;
    for (int i = tid; i < D; i += 256) s += x[i];
    red[tid] = s; __syncthreads();
    for (int st = 128; st > 0; st >>= 1) { if (tid < st) red[tid] += red[tid+st]; __syncthreads(); }
    float mu = red[0] / D;
    __syncthreads();
    float v = 0.f;
    for (int i = tid; i < D; i += 256) { float d = x[i] - mu; v += d*d; }
    red[tid] = v; __syncthreads();
    for (int st = 128; st > 0; st >>= 1) { if (tid < st) red[tid] += red[tid+st]; __syncthreads(); }
    float rs = rsqrtf(red[0]/D + 1e-5f);
    __syncthreads();
    for (int i = tid; i < D; i += 256)
        out[t*D + i] = __float2bfloat16((x[i] - mu) * rs * w[i] + bb[i]);
}

// ============================================================================
// bf16 GEMM, 2-stage cp.async pipeline, fp32 accumulate, templated output.
//   BTRANS=0: C = A[M,K] * B[N,K]^T      (both k-major bf16)
//   BTRANS=1: C = A[M,K] * B[K,N]        (B row-major [K,N] bf16)
//   ACT=1: exact GELU. bias optional (per-n, fp32, batch stride sBias).
// BK=32. 256 threads = 8 warps, warp tile WM x WN.
// ============================================================================
template<int BM, int BN, int WM, int WN, int BTRANS, int ACT, typename OutT>
__global__ void __launch_bounds__(256) bgemm(
    const bf16* __restrict__ A, int lda, long long sA,
    const bf16* __restrict__ B, int ldb, long long sB,
    const float* __restrict__ bias, long long sBias,
    OutT* __restrict__ C, int ldc, long long sC, int K)
{
    constexpr int BK = 32;
    constexpr int BKP = 40;                 // padded (80 B rows, 16B aligned, LDSM-safe)
    constexpr int BNP = BN + 8;
    constexpr int BS_ELEMS = BTRANS ? BK * BNP : BN * BKP;
    __shared__ bf16 As[2][BM * BKP];
    __shared__ bf16 Bs[2][BS_ELEMS];

    int z = blockIdx.z;
    A += (long long)z * sA; B += (long long)z * sB; C += (long long)z * sC;
    int bm = blockIdx.y * BM, bn = blockIdx.x * BN;
    int tid = threadIdx.x, wid = tid >> 5, lane = tid & 31;
    constexpr int WCOLS = BN / WN;
    int wm0 = (wid / WCOLS) * WM;
    int wn0 = (wid % WCOLS) * WN;
    constexpr int MF = WM/16, NF = WN/16;

    wmma::fragment<wmma::accumulator,16,16,16,float> fc[MF][NF];
#pragma unroll
    for (int i = 0; i < MF; i++)
#pragma unroll
        for (int j = 0; j < NF; j++) wmma::fill_fragment(fc[i][j], 0.0f);

    uint32_t asm_base[2] = { smem_u32(&As[0][0]), smem_u32(&As[1][0]) };
    uint32_t bsm_base[2] = { smem_u32(&Bs[0][0]), smem_u32(&Bs[1][0]) };

    auto issue_stage = [&](int s, int k0) {
        // A: BM rows x 32 elems (64 B = 4 chunks/row)
#pragma unroll
        for (int c = tid; c < BM*4; c += 256) {
            int row = c >> 2, ch = c & 3;
            CP_ASYNC16(asm_base[s] + (row*BKP + ch*8)*2,
                       A + (long long)(bm + row)*lda + k0 + ch*8);
        }
        if (BTRANS == 0) {
#pragma unroll
            for (int c = tid; c < BN*4; c += 256) {
                int row = c >> 2, ch = c & 3;
                CP_ASYNC16(bsm_base[s] + (row*BKP + ch*8)*2,
                           B + (long long)(bn + row)*ldb + k0 + ch*8);
            }
        } else {
            // B tile: BK rows x BN cols
#pragma unroll
            for (int c = tid; c < BK*(BN/8); c += 256) {
                int k = c / (BN/8), ch = c % (BN/8);
                CP_ASYNC16(bsm_base[s] + (k*BNP + ch*8)*2,
                           B + (long long)(k0 + k)*ldb + bn + ch*8);
            }
        }
    };

    int KT = K / BK;
    issue_stage(0, 0);
    CP_COMMIT();

    for (int kt = 0; kt < KT; kt++) {
        if (kt + 1 < KT) issue_stage((kt + 1) & 1, (kt + 1) * BK);
        CP_COMMIT();
        CP_WAIT1();
        __syncthreads();
        int cur = kt & 1;
#pragma unroll
        for (int kk = 0; kk < BK; kk += 16) {
            wmma::fragment<wmma::matrix_a,16,16,16,bf16,wmma::row_major> fa[MF];
#pragma unroll
            for (int i = 0; i < MF; i++)
                wmma::load_matrix_sync(fa[i], &As[cur][(wm0 + i*16)*BKP + kk], BKP);
            if (BTRANS == 0) {
                wmma::fragment<wmma::matrix_b,16,16,16,bf16,wmma::col_major> fb[NF];
#pragma unroll
                for (int j = 0; j < NF; j++)
                    wmma::load_matrix_sync(fb[j], &Bs[cur][(wn0 + j*16)*BKP + kk], BKP);
#pragma unroll
                for (int i = 0; i < MF; i++)
#pragma unroll
                    for (int j = 0; j < NF; j++)
                        wmma::mma_sync(fc[i][j], fa[i], fb[j], fc[i][j]);
            } else {
                wmma::fragment<wmma::matrix_b,16,16,16,bf16,wmma::row_major> fb[NF];
#pragma unroll
                for (int j = 0; j < NF; j++)
                    wmma::load_matrix_sync(fb[j], &Bs[cur][kk*BNP + wn0 + j*16], BNP);
#pragma unroll
                for (int i = 0; i < MF; i++)
#pragma unroll
                    for (int j = 0; j < NF; j++)
                        wmma::mma_sync(fc[i][j], fa[i], fb[j], fc[i][j]);
            }
        }
        __syncthreads();
    }

    // epilogue: reuse As smem as per-warp fp32 staging (8 warps x 256 floats)
    float* st = reinterpret_cast<float*>(&As[0][0]) + wid * 256;
#pragma unroll
    for (int i = 0; i < MF; i++) {
#pragma unroll
        for (int j = 0; j < NF; j++) {
            wmma::store_matrix_sync(st, fc[i][j], 16, wmma::mem_row_major);
            __syncwarp();
            int m0 = bm + wm0 + i*16, n0 = bn + wn0 + j*16;
#pragma unroll
            for (int e = 0; e < 8; e++) {
                int idx = e*32 + lane;
                int r = idx >> 4, c = idx & 15;
                float val = st[idx];
                int n = n0 + c;
                if (bias) val += bias[(long long)z*sBias + n];
                if (ACT == 1) val = gelu_exact(val);
                C[(long long)(m0 + r)*ldc + n] = to_out<OutT>(val);
            }
            __syncwarp();
        }
    }
}

// ---------------- v = einsum('ij,tjd->itd', v_fact, xt_heads) -------------
__global__ void vproj_kernel(const float* __restrict__ xt, const float* __restrict__ vf,
                             float* __restrict__ v) {
    int t = blockIdx.x, h = blockIdx.y, d = threadIdx.x;   // 64 threads
    float acc = 0.f;
#pragma unroll
    for (int j = 0; j < H; j++) acc += vf[h*H + j] * xt[t*D + j*HD + d];
    v[(h*T + t)*HD + d] = acc;
}

// ---------------- causal attention with ALiBi, one block per (qi, h) ------
__global__ void attn_kernel(const float* __restrict__ qk, const float* __restrict__ v,
                            float* __restrict__ y) {
    int qi = blockIdx.x, h = blockIdx.y;
    int tid = threadIdx.x;                 // 128
    __shared__ float qrow[HD];
    __shared__ float sc[T];
    __shared__ float red[128];
    __shared__ float part[2][HD];
    if (tid < HD) qrow[tid] = qk[(long long)qi*(2*D) + h*HD + tid];
    __syncthreads();
    float slope = c_slopes[h];
    float m = -INFINITY;
    for (int j = tid; j <= qi; j += 128) {
        const float4* k4 = (const float4*)(qk + (long long)j*(2*D) + D + h*HD);
        float dot = 0.f;
#pragma unroll
        for (int e = 0; e < 16; e++) {
            float4 kv = k4[e];
            dot += qrow[e*4+0]*kv.x + qrow[e*4+1]*kv.y + qrow[e*4+2]*kv.z + qrow[e*4+3]*kv.w;
        }
        float s = dot * 0.125f + slope * (float)(j - qi);
        sc[j] = s;
        m = fmaxf(m, s);
    }
    red[tid] = m; __syncthreads();
    for (int st = 64; st > 0; st >>= 1) { if (tid < st) red[tid] = fmaxf(red[tid], red[tid+st]); __syncthreads(); }
    m = red[0];
    __syncthreads();
    float lsum = 0.f;
    for (int j = tid; j <= qi; j += 128) { float p = expf(sc[j] - m); sc[j] = p; lsum += p; }
    red[tid] = lsum; __syncthreads();
    for (int st = 64; st > 0; st >>= 1) { if (tid < st) red[tid] += red[tid+st]; __syncthreads(); }
    float inv = 1.0f / red[0];
    __syncthreads();
    {
        int e = tid & 63, hf = tid >> 6;   // split j over 2 halves
        const float* vh = v + (long long)h*T*HD;
        float acc = 0.f;
        for (int j = hf; j <= qi; j += 2) acc += sc[j] * vh[j*HD + e];
        part[hf][e] = acc;
    }
    __syncthreads();
    if (tid < HD)
        y[((long long)h*T + qi)*HD + tid] = (part[0][tid] + part[1][tid]) * inv;
}

// ---------------- xt_new = xt + out_fact-lift(y) --------------------------
__global__ void mixout_kernel(const float* __restrict__ xt, const float* __restrict__ of,
                              const float* __restrict__ y, float* __restrict__ xt_new) {
    int t = blockIdx.x, c = threadIdx.x;   // 768 threads
    int i = c >> 6, d = c & 63;
    float acc = xt[t*D + c];
#pragma unroll
    for (int j = 0; j < H; j++) acc += of[i*H + j] * y[((long long)j*T + t)*HD + d];
    xt_new[t*D + c] = acc;
}

// ---------------- per-head LN over 64 (dual fp32 + bf16 output) -----------
__global__ void dln_kernel(const float* __restrict__ p, const float* __restrict__ w,
                           const float* __restrict__ b, float* __restrict__ xhat,
                           bf16* __restrict__ xhat_bf) {
    int row = blockIdx.x;                  // h*T + t
    int h = row >> 10;
    int tid = threadIdx.x;                 // 64
    __shared__ float r[64];
    float x = p[(long long)row*HD + tid];
    r[tid] = x; __syncthreads();
    for (int st = 32; st > 0; st >>= 1) { if (tid < st) r[tid] += r[tid+st]; __syncthreads(); }
    float mu = r[0] / HD;
    __syncthreads();
    float d = x - mu;
    r[tid] = d*d; __syncthreads();
    for (int st = 32; st > 0; st >>= 1) { if (tid < st) r[tid] += r[tid+st]; __syncthreads(); }
    float rs = rsqrtf(r[0]/HD + 1e-5f);
    float val = d * rs * w[h*HD + tid] + b[h*HD + tid];
    xhat[(long long)row*HD + tid] = val;
    xhat_bf[(long long)row*HD + tid] = __float2bfloat16(val);
}

// ---------------- in-place softmax over V=8192 (+ bf16 copy) --------------
__global__ void dsoftmax_kernel(float* __restrict__ dw, bf16* __restrict__ pb) {
    long long row = blockIdx.x;            // 12288 rows
    float* p = dw + row * V;
    bf16* pbr = pb + row * V;
    int tid = threadIdx.x;                 // 256
    __shared__ float sh[V];
    __shared__ float red[256];
    float m = -INFINITY;
    for (int i = tid; i < V; i += 256) { float x = p[i]; sh[i] = x; m = fmaxf(m, x); }
    red[tid] = m; __syncthreads();
    for (int st = 128; st > 0; st >>= 1) { if (tid < st) red[tid] = fmaxf(red[tid], red[tid+st]); __syncthreads(); }
    m = red[0];
    __syncthreads();
    float s = 0.f;
    for (int i = tid; i < V; i += 256) { float e = expf(sh[i] - m); sh[i] = e; s += e; }
    red[tid] = s; __syncthreads();
    for (int st = 128; st > 0; st >>= 1) { if (tid < st) red[tid] += red[tid+st]; __syncthreads(); }
    float inv = 1.0f / red[0];
    __syncthreads();
    for (int i = tid; i < V; i += 256) {
        float val = sh[i] * inv;
        p[i] = val;
        pbr[i] = __float2bfloat16(val);
    }
}

// ---------------- loss + xe_new -------------------------------------------
__global__ void zero_loss_kernel(float* loss) { *loss = 0.f; }

__global__ void loss_kernel(const float* __restrict__ xhat, const float* __restrict__ recon,
                            float* __restrict__ loss) {
    int row = blockIdx.x;                  // 12288
    int tid = threadIdx.x;                 // 64
    __shared__ float r[64];
    float d = xhat[(long long)row*HD + tid] - recon[(long long)row*HD + tid];
    r[tid] = d*d; __syncthreads();
    for (int st = 32; st > 0; st >>= 1) { if (tid < st) r[tid] += r[tid+st]; __syncthreads(); }
    if (tid == 0) atomicAdd(loss, r[0] * (1.0f / (float)(H*T*HD)));
}

__global__ void xenew_kernel(const float* __restrict__ xe, const float* __restrict__ recon,
                             float* __restrict__ out_xe) {
    int t = blockIdx.x, c = threadIdx.x;   // 768
    int h = c >> 6, e = c & 63;
    out_xe[t*D + c] = xe[t*D + c] + recon[((long long)h*T + t)*HD + e];
}

// ---------------- launch ---------------------------------------------------
extern "C" void kernel_launch(void* const* d_in, const int* in_sizes, int n_in,
                              void* d_out, int out_size) {
    const float* xt      = (const float*)d_in[0];
    const float* xe      = (const float*)d_in[1];
    const float* ln1_w   = (const float*)d_in[2];
    const float* ln1_b   = (const float*)d_in[3];
    const float* qk_w    = (const float*)d_in[4];
    const float* qk_b    = (const float*)d_in[5];
    const float* v_fact  = (const float*)d_in[6];
    const float* out_fact= (const float*)d_in[7];
    const float* ln2_w   = (const float*)d_in[8];
    const float* ln2_b   = (const float*)d_in[9];
    const float* fc_w    = (const float*)d_in[10];
    const float* fc_b    = (const float*)d_in[11];
    const float* proj_w  = (const float*)d_in[12];
    const float* proj_b  = (const float*)d_in[13];
    const float* dln_w   = (const float*)d_in[14];
    const float* dln_b   = (const float*)d_in[15];
    const float* dict_emb= (const float*)d_in[16];

    float* out = (float*)d_out;
    float* out_xt = out;                       // [T,D]
    float* out_xe = out + (size_t)T*D;         // [T,D]
    float* out_dw = out + (size_t)2*T*D;       // [H,T,V]
    float* out_loss = out + (size_t)2*T*D + (size_t)H*T*V; // scalar

    bf16 *xnorm_bf, *qkw_bf, *fcw_bf, *projw_bf, *dict_bf, *x2_bf, *h_bf, *xhat_bf, *probs_bf;
    float *qkbuf, *vbuf, *ybuf, *pbuf, *xhat, *recon;
    cudaGetSymbolAddress((void**)&xnorm_bf, g_xnorm_bf);
    cudaGetSymbolAddress((void**)&qkbuf, g_qk);
    cudaGetSymbolAddress((void**)&qkw_bf, g_qkw_bf);
    cudaGetSymbolAddress((void**)&fcw_bf, g_fcw_bf);
    cudaGetSymbolAddress((void**)&projw_bf, g_projw_bf);
    cudaGetSymbolAddress((void**)&dict_bf, g_dict_bf);
    cudaGetSymbolAddress((void**)&x2_bf, g_x2_bf);
    cudaGetSymbolAddress((void**)&h_bf, g_h_bf);
    cudaGetSymbolAddress((void**)&vbuf,  g_v);
    cudaGetSymbolAddress((void**)&ybuf,  g_y);
    cudaGetSymbolAddress((void**)&pbuf,  g_proj);
    cudaGetSymbolAddress((void**)&xhat,  g_xhat);
    cudaGetSymbolAddress((void**)&xhat_bf, g_xhat_bf);
    cudaGetSymbolAddress((void**)&probs_bf, g_probs_bf);
    cudaGetSymbolAddress((void**)&recon, g_recon);

    // 0. weight conversions fp32 -> bf16
    f2bf_kernel<<<(2*D*D/8 + 255)/256, 256>>>((const float4*)qk_w, (uint4*)qkw_bf, 2*D*D/8);
    f2bf_kernel<<<((int)((size_t)NFF*D/8) + 255)/256, 256>>>((const float4*)fc_w, (uint4*)fcw_bf, (int)((size_t)NFF*D/8));
    f2bf_kernel<<<(H*HD*FF/8 + 255)/256, 256>>>((const float4*)proj_w, (uint4*)projw_bf, H*HD*FF/8);
    f2bf_kernel<<<(H*V*HD/8 + 255)/256, 256>>>((const float4*)dict_emb, (uint4*)dict_bf, H*V*HD/8);

    // 1. x_norm = LN1(xt + xe)  (bf16)
    ln768_kernel<<<T, 256>>>(xt, xe, ln1_w, ln1_b, xnorm_bf);
    // 2. qk = x_norm @ qk_w^T + qk_b   [1024, 1536] fp32
    bgemm<128,128,64,32,0,0,float><<<dim3(2*D/128, T/128, 1), 256>>>(
        xnorm_bf, D, 0, qkw_bf, D, 0, qk_b, 0, qkbuf, 2*D, 0, D);
    // 3. v lift
    vproj_kernel<<<dim3(T, H), HD>>>(xt, v_fact, vbuf);
    // 4. attention
    attn_kernel<<<dim3(T, H), 128>>>(qkbuf, vbuf, ybuf);
    // 5. xt_new = xt + out_fact-lift(y)   -> d_out
    mixout_kernel<<<T, D>>>(xt, out_fact, ybuf, out_xt);
    // 6. x2 = LN2(xt_new + xe)  (bf16)
    ln768_kernel<<<T, 256>>>(out_xt, xe, ln2_w, ln2_b, x2_bf);
    // 7. h = gelu(x2 @ fc_w^T + fc_b)   [1024, 36864] bf16
    bgemm<128,128,64,32,0,1,bf16><<<dim3(NFF/128, T/128, 1), 256>>>(
        x2_bf, D, 0, fcw_bf, D, 0, fc_b, 0, h_bf, NFF, 0, D);
    // 8. proj (batched over heads): [1024,64] per head, K=3072
    bgemm<128,64,32,32,0,0,float><<<dim3(1, T/128, H), 256>>>(
        h_bf, NFF, FF, projw_bf, FF, (long long)HD*FF,
        proj_b, HD, pbuf, HD, (long long)T*HD, FF);
    // 9. per-head LN (fp32 + bf16)
    dln_kernel<<<H*T, HD>>>(pbuf, dln_w, dln_b, xhat, xhat_bf);
    // 10. dict logits -> out_dw  (batched, K=64)
    bgemm<128,128,64,32,0,0,float><<<dim3(V/128, T/128, H), 256>>>(
        xhat_bf, HD, (long long)T*HD, dict_bf, HD, (long long)V*HD,
        nullptr, 0, out_dw, V, (long long)T*V, HD);
    // 11. softmax in place + bf16 copy
    dsoftmax_kernel<<<H*T, 256>>>(out_dw, probs_bf);
    // 12. recon = probs @ dict_emb  (batched, B is [K=V, N=HD] row-major)
    bgemm<128,64,32,32,1,0,float><<<dim3(1, T/128, H), 256>>>(
        probs_bf, V, (long long)T*V, dict_bf, HD, (long long)V*HD,
        nullptr, 0, recon, HD, (long long)T*HD, V);
    // 13/14. loss
    zero_loss_kernel<<<1, 1>>>(out_loss);
    loss_kernel<<<H*T, HD>>>(xhat, recon, out_loss);
    // 15. xe_new
    xenew_kernel<<<T, D>>>(xe, recon, out_xe);
}